// round 1
// baseline (speedup 1.0000x reference)
#include <cuda_runtime.h>
#include <math.h>
#include <stdint.h>

// ---------------- problem constants ----------------
#define T       4096
#define HID     400
#define G4      1600          // 4*HID
#define EMB     50
#define E3      150           // 3*EMB
#define KEY     300
#define K4      1200          // 4*KEY
#define SENT    0x7F800001u   // NaN sentinel ("not written yet")

// rtoken: T*E3 = 614400 floats; ktoken: 400; context: T*32*HID = 52428800
#define OFF_KTOK  614400
#define OFF_CTX   614800

// ---------------- scratch (static device globals; no allocation) ----------------
__device__ float g_xg0[(size_t)T * G4];      // precomputed input gates layer0 (+both biases)
__device__ float g_h0[(T + 1) * HID];        // h0 timeline, slot 0 = zeros
__device__ float g_h1[(T + 1) * HID];        // h1 timeline (== rnn_out shifted by 1)
__device__ float g_kgate[K4];                // key lstm pre-activation gates

// ---------------- helpers ----------------
__device__ __forceinline__ float sigf(float x) {
    return __fdividef(1.f, 1.f + __expf(-x));
}
__device__ __forceinline__ float tanhf_(float x) {
    x = fminf(15.f, fmaxf(-15.f, x));
    float e = __expf(-2.f * x);
    return __fdividef(1.f - e, 1.f + e);
}
__device__ __forceinline__ float wsum(float v) {
#pragma unroll
    for (int o = 16; o > 0; o >>= 1) v += __shfl_xor_sync(0xffffffffu, v, o);
    return v;
}

// ---------------- init: sentinel-fill h timelines, zero slot 0 ----------------
__global__ void init_kernel() {
    int i = blockIdx.x * blockDim.x + threadIdx.x;
    if (i >= (T + 1) * HID) return;
    float v = (i < HID) ? 0.f : __uint_as_float(SENT);
    g_h0[i] = v;
    g_h1[i] = v;
}

// ---------------- kernel A: xg0 = concat-embed @ Wih0^T + bih0 + bhh0 ----------------
// GEMM (4096 x 1600, K=150). Tiles: BT=64, BR=160, 256 threads, 8x5 register tile.
// K chunks of 50 align exactly with the three embedding tables.
__global__ void __launch_bounds__(256, 1) xg0_kernel(
    const int* __restrict__ xr, const int* __restrict__ xcpc, const int* __restrict__ xma,
    const float* __restrict__ em, const float* __restrict__ ec, const float* __restrict__ er,
    const float* __restrict__ Wih0, const float* __restrict__ bih0, const float* __restrict__ bhh0)
{
    __shared__ float xs[64][53];
    __shared__ float ws[160][53];
    const int bt0 = blockIdx.x * 64;
    const int br0 = blockIdx.y * 160;
    const int tid = threadIdx.x;
    float acc[8][5];
#pragma unroll
    for (int i = 0; i < 8; i++)
#pragma unroll
        for (int r = 0; r < 5; r++) acc[i][r] = 0.f;

    for (int ch = 0; ch < 3; ch++) {
        const float* tab = (ch == 0) ? em : ((ch == 1) ? ec : er);
        const int* idx = (ch == 0) ? xma : ((ch == 1) ? xcpc : xr);
        for (int i = tid; i < 64 * 50; i += 256) {
            int tt = i / 50, kk = i - tt * 50;
            xs[tt][kk] = tab[idx[bt0 + tt] * EMB + kk];
        }
        for (int i = tid; i < 160 * 50; i += 256) {
            int rr = i / 50, kk = i - rr * 50;
            ws[rr][kk] = Wih0[(br0 + rr) * E3 + ch * 50 + kk];
        }
        __syncthreads();
        const int tr = tid & 31, tc = tid >> 5;
#pragma unroll 5
        for (int kk = 0; kk < 50; kk++) {
            float a[8], wv[5];
#pragma unroll
            for (int i = 0; i < 8; i++) a[i] = xs[tc * 8 + i][kk];
#pragma unroll
            for (int r = 0; r < 5; r++) wv[r] = ws[tr * 5 + r][kk];
#pragma unroll
            for (int i = 0; i < 8; i++)
#pragma unroll
                for (int r = 0; r < 5; r++) acc[i][r] = fmaf(a[i], wv[r], acc[i][r]);
        }
        __syncthreads();
    }
    const int tr = tid & 31, tc = tid >> 5;
#pragma unroll
    for (int r = 0; r < 5; r++) {
        int rg = br0 + tr * 5 + r;
        float bias = bih0[rg] + bhh0[rg];
#pragma unroll
        for (int i = 0; i < 8; i++) {
            int t = bt0 + tc * 8 + i;
            g_xg0[(size_t)t * G4 + rg] = acc[i][r] + bias;
        }
    }
}

// ---------------- kernel B: persistent dual-layer LSTM recurrence ----------------
// blocks 0..39:   layer0, 10 warps each, warp owns one j (4 gate rows x K=400)
// blocks 40..139: layer1, 4 warps each, warp owns one j (4 gate rows x K=800: [Wih1|Whh1])
// inter-CTA sync: NaN-sentinel polling on g_h0/g_h1 through L2 (__stcg / __ldcv).
__global__ void __launch_bounds__(320, 1) lstm_main_kernel(
    const float* __restrict__ Whh0,
    const float* __restrict__ Wih1,
    const float* __restrict__ Whh1,
    const float* __restrict__ bih1,
    const float* __restrict__ bhh1)
{
    const int warp = threadIdx.x >> 5;
    const int lane = threadIdx.x & 31;

    if (blockIdx.x < 40) {
        // ---------------- layer 0 ----------------
        const int j = blockIdx.x * 10 + warp;
        float w0[13], w1[13], w2[13], w3[13];
#pragma unroll
        for (int c = 0; c < 13; c++) {
            int k = lane + 32 * c;
            bool v = (k < HID);
            w0[c] = v ? Whh0[(j) * HID + k] : 0.f;
            w1[c] = v ? Whh0[(j + 400) * HID + k] : 0.f;
            w2[c] = v ? Whh0[(j + 800) * HID + k] : 0.f;
            w3[c] = v ? Whh0[(j + 1200) * HID + k] : 0.f;
        }
        float cst = 0.f;
        for (int t = 0; t < T; t++) {
            const float* hb = g_h0 + t * HID;
            float hv[13];
#pragma unroll
            for (int c = 0; c < 13; c++) {
                int k = lane + 32 * c;
                hv[c] = (k < HID) ? __ldcv(hb + k) : 0.f;
            }
            for (;;) {
                unsigned bad = 0;
#pragma unroll
                for (int c = 0; c < 13; c++) {
                    int k = lane + 32 * c;
                    if (k < HID && __float_as_uint(hv[c]) == SENT) {
                        hv[c] = __ldcv(hb + k);
                        bad |= (unsigned)(__float_as_uint(hv[c]) == SENT);
                    }
                }
                if (!bad) break;
            }
            float a0 = 0.f, a1 = 0.f, a2 = 0.f, a3 = 0.f;
#pragma unroll
            for (int c = 0; c < 13; c++) {
                a0 = fmaf(w0[c], hv[c], a0);
                a1 = fmaf(w1[c], hv[c], a1);
                a2 = fmaf(w2[c], hv[c], a2);
                a3 = fmaf(w3[c], hv[c], a3);
            }
            a0 = wsum(a0); a1 = wsum(a1); a2 = wsum(a2); a3 = wsum(a3);
            const float* xg = g_xg0 + (size_t)t * G4 + j;
            float gi = a0 + __ldg(xg);
            float gf = a1 + __ldg(xg + 400);
            float gg = a2 + __ldg(xg + 800);
            float go = a3 + __ldg(xg + 1200);
            cst = sigf(gf) * cst + sigf(gi) * tanhf_(gg);
            float h = sigf(go) * tanhf_(cst);
            if (lane == 0) __stcg(g_h0 + (t + 1) * HID + j, h);
        }
    } else {
        // ---------------- layer 1 ----------------
        if (warp >= 4) return;
        const int j = (blockIdx.x - 40) * 4 + warp;
        float w0[25], w1[25], w2[25], w3[25];
#pragma unroll
        for (int c = 0; c < 25; c++) {
            int k = lane + 32 * c;
            if (k < HID) {
                w0[c] = Wih1[(j) * HID + k];
                w1[c] = Wih1[(j + 400) * HID + k];
                w2[c] = Wih1[(j + 800) * HID + k];
                w3[c] = Wih1[(j + 1200) * HID + k];
            } else {
                int kk = k - HID;
                w0[c] = Whh1[(j) * HID + kk];
                w1[c] = Whh1[(j + 400) * HID + kk];
                w2[c] = Whh1[(j + 800) * HID + kk];
                w3[c] = Whh1[(j + 1200) * HID + kk];
            }
        }
        float b0 = bih1[j] + bhh1[j];
        float b1 = bih1[j + 400] + bhh1[j + 400];
        float b2 = bih1[j + 800] + bhh1[j + 800];
        float b3 = bih1[j + 1200] + bhh1[j + 1200];
        float cst = 0.f;
        for (int t = 0; t < T; t++) {
            const float* h0b = g_h0 + (t + 1) * HID;   // h0[t] (produced this step by layer0)
            const float* h1b = g_h1 + t * HID;         // h1[t-1]
            float hv[25];
#pragma unroll
            for (int c = 0; c < 25; c++) {
                int k = lane + 32 * c;
                hv[c] = __ldcv(k < HID ? h0b + k : h1b + (k - HID));
            }
            for (;;) {
                unsigned bad = 0;
#pragma unroll
                for (int c = 0; c < 25; c++) {
                    int k = lane + 32 * c;
                    if (__float_as_uint(hv[c]) == SENT) {
                        hv[c] = __ldcv(k < HID ? h0b + k : h1b + (k - HID));
                        bad |= (unsigned)(__float_as_uint(hv[c]) == SENT);
                    }
                }
                if (!bad) break;
            }
            float a0 = 0.f, a1 = 0.f, a2 = 0.f, a3 = 0.f;
#pragma unroll
            for (int c = 0; c < 25; c++) {
                a0 = fmaf(w0[c], hv[c], a0);
                a1 = fmaf(w1[c], hv[c], a1);
                a2 = fmaf(w2[c], hv[c], a2);
                a3 = fmaf(w3[c], hv[c], a3);
            }
            a0 = wsum(a0); a1 = wsum(a1); a2 = wsum(a2); a3 = wsum(a3);
            float gi = a0 + b0, gf = a1 + b1, gg = a2 + b2, go = a3 + b3;
            cst = sigf(gf) * cst + sigf(gi) * tanhf_(gg);
            float h = sigf(go) * tanhf_(cst);
            if (lane == 0) __stcg(g_h1 + (t + 1) * HID + j, h);
        }
    }
}

// ---------------- kernel C: rtoken = rnn_out @ fcW^T + fcb ----------------
// GEMM (4096 x 150, K=400). Same tiling as kernel A, rows padded 150->160 w/ guards.
__global__ void __launch_bounds__(256, 1) rtoken_kernel(
    const float* __restrict__ fcW, const float* __restrict__ fcb, float* __restrict__ out)
{
    __shared__ float xs[64][53];
    __shared__ float ws[160][53];
    const int bt0 = blockIdx.x * 64;
    const int tid = threadIdx.x;
    float acc[8][5];
#pragma unroll
    for (int i = 0; i < 8; i++)
#pragma unroll
        for (int r = 0; r < 5; r++) acc[i][r] = 0.f;

    for (int ch = 0; ch < 8; ch++) {
        int k0 = ch * 50;
        for (int i = tid; i < 64 * 50; i += 256) {
            int tt = i / 50, kk = i - tt * 50;
            xs[tt][kk] = g_h1[(size_t)(bt0 + tt + 1) * HID + k0 + kk];
        }
        for (int i = tid; i < 160 * 50; i += 256) {
            int rr = i / 50, kk = i - rr * 50;
            ws[rr][kk] = (rr < E3) ? fcW[rr * HID + k0 + kk] : 0.f;
        }
        __syncthreads();
        const int tr = tid & 31, tc = tid >> 5;
#pragma unroll 5
        for (int kk = 0; kk < 50; kk++) {
            float a[8], wv[5];
#pragma unroll
            for (int i = 0; i < 8; i++) a[i] = xs[tc * 8 + i][kk];
#pragma unroll
            for (int r = 0; r < 5; r++) wv[r] = ws[tr * 5 + r][kk];
#pragma unroll
            for (int i = 0; i < 8; i++)
#pragma unroll
                for (int r = 0; r < 5; r++) acc[i][r] = fmaf(a[i], wv[r], acc[i][r]);
        }
        __syncthreads();
    }
    const int tr = tid & 31, tc = tid >> 5;
#pragma unroll
    for (int r = 0; r < 5; r++) {
        int rg = tr * 5 + r;
        if (rg < E3) {
            float bias = fcb[rg];
#pragma unroll
            for (int i = 0; i < 8; i++) {
                int t = bt0 + tc * 8 + i;
                out[(size_t)t * E3 + rg] = acc[i][r] + bias;
            }
        }
    }
}

// ---------------- kernel D: context fill ----------------
// stack scan is degenerate: context[t,0,:] = softmax(logits)[0] * sigmoid(D.rnn), rest zero.
__global__ void __launch_bounds__(128, 1) ctx_kernel(
    const float* __restrict__ actW, const float* __restrict__ actb,
    const float* __restrict__ Dp, float* __restrict__ out)
{
    const int t = blockIdx.x;
    const int warp = threadIdx.x >> 5, lane = threadIdx.x & 31;
    __shared__ float red[4];
    const float* hr = g_h1 + (size_t)(t + 1) * HID;
    const float* wrow = (warp < 3) ? (actW + warp * HID) : Dp;
    float acc = 0.f;
#pragma unroll
    for (int c = 0; c < 13; c++) {
        int k = lane + 32 * c;
        if (k < HID) acc = fmaf(__ldg(wrow + k), __ldg(hr + k), acc);
    }
    acc = wsum(acc);
    if (lane == 0) red[warp] = acc + ((warp < 3) ? actb[warp] : 0.f);
    __syncthreads();
    float l0 = red[0], l1 = red[1], l2 = red[2], d = red[3];
    float m = fmaxf(l0, fmaxf(l1, l2));
    float e0 = __expf(l0 - m), e1 = __expf(l1 - m), e2 = __expf(l2 - m);
    float p0 = __fdividef(e0, e0 + e1 + e2);
    float v = p0 * sigf(d);

    float4* dst = (float4*)(out + OFF_CTX + (size_t)t * 32 * HID);
    float4 vz = make_float4(v, v, v, v);
    float4 z = make_float4(0.f, 0.f, 0.f, 0.f);
    for (int q = threadIdx.x; q < 3200; q += 128) {
        __stcs(dst + q, (q < 100) ? vz : z);   // first 400 floats = slot 0, rest zero
    }
}

// ---------------- kernel E1: key lstm gates = key_Wih @ rh + bih + bhh ----------------
__global__ void __launch_bounds__(128, 1) keygate_kernel(
    const float* __restrict__ kWih, const float* __restrict__ kbih, const float* __restrict__ kbhh)
{
    const int gw = blockIdx.x * 4 + (threadIdx.x >> 5);  // 40 global warps
    const int lane = threadIdx.x & 31;
    const float* hr = g_h1 + (size_t)T * HID;            // rh = final h1
    float hv[13];
#pragma unroll
    for (int c = 0; c < 13; c++) {
        int k = lane + 32 * c;
        hv[c] = (k < HID) ? __ldg(hr + k) : 0.f;
    }
    for (int rr = 0; rr < 30; rr++) {
        int r = gw * 30 + rr;
        float acc = 0.f;
#pragma unroll
        for (int c = 0; c < 13; c++) {
            int k = lane + 32 * c;
            if (k < HID) acc = fmaf(__ldg(kWih + (size_t)r * HID + k), hv[c], acc);
        }
        acc = wsum(acc);
        if (lane == 0) g_kgate[r] = acc + kbih[r] + kbhh[r];
    }
}

// ---------------- kernel E2: kh nonlinearity + ktoken = key_fcW @ kh + key_fcb ----------------
__global__ void __launch_bounds__(512, 1) keyout_kernel(
    const float* __restrict__ kfcW, const float* __restrict__ kfcb, float* __restrict__ out)
{
    __shared__ float kh[KEY];
    const int tid = threadIdx.x;
    if (tid < KEY) {
        float gi = g_kgate[tid], gg = g_kgate[600 + tid], go = g_kgate[900 + tid];
        float c = sigf(gi) * tanhf_(gg);   // c0 = 0 so forget term vanishes
        kh[tid] = sigf(go) * tanhf_(c);
    }
    __syncthreads();
    const int warp = tid >> 5, lane = tid & 31;  // 16 warps x 25 rows = 400
    for (int rr = 0; rr < 25; rr++) {
        int r = warp * 25 + rr;
        float acc = 0.f;
#pragma unroll
        for (int c = 0; c < 10; c++) {
            int k = lane + 32 * c;
            if (k < KEY) acc = fmaf(__ldg(kfcW + (size_t)r * KEY + k), kh[k], acc);
        }
        acc = wsum(acc);
        if (lane == 0) out[OFF_KTOK + r] = acc + kfcb[r];
    }
}

// ---------------- launch ----------------
extern "C" void kernel_launch(void* const* d_in, const int* in_sizes, int n_in,
                              void* d_out, int out_size)
{
    const int*   xr       = (const int*)d_in[0];
    const int*   xcpc     = (const int*)d_in[1];
    const int*   xma      = (const int*)d_in[2];
    const float* em       = (const float*)d_in[3];
    const float* ec       = (const float*)d_in[4];
    const float* er       = (const float*)d_in[5];
    const float* Wih0     = (const float*)d_in[6];
    const float* Whh0     = (const float*)d_in[7];
    const float* bih0     = (const float*)d_in[8];
    const float* bhh0     = (const float*)d_in[9];
    const float* Wih1     = (const float*)d_in[10];
    const float* Whh1     = (const float*)d_in[11];
    const float* bih1     = (const float*)d_in[12];
    const float* bhh1     = (const float*)d_in[13];
    const float* fcW      = (const float*)d_in[14];
    const float* fcb      = (const float*)d_in[15];
    const float* actW     = (const float*)d_in[16];
    const float* actb     = (const float*)d_in[17];
    const float* Dp       = (const float*)d_in[18];
    const float* kWih     = (const float*)d_in[19];
    // d_in[20] key_Whh unused (h_prev = 0), d_in[21..22] biases, 23..24 fc
    const float* kbih     = (const float*)d_in[21];
    const float* kbhh     = (const float*)d_in[22];
    const float* kfcW     = (const float*)d_in[23];
    const float* kfcb     = (const float*)d_in[24];
    float* out = (float*)d_out;

    init_kernel<<<((T + 1) * HID + 255) / 256, 256>>>();
    xg0_kernel<<<dim3(T / 64, G4 / 160), 256>>>(xr, xcpc, xma, em, ec, er, Wih0, bih0, bhh0);
    lstm_main_kernel<<<140, 320>>>(Whh0, Wih1, Whh1, bih1, bhh1);
    rtoken_kernel<<<T / 64, 256>>>(fcW, fcb, out);
    ctx_kernel<<<T, 128>>>(actW, actb, Dp, out);
    keygate_kernel<<<10, 128>>>(kWih, kbih, kbhh);
    keyout_kernel<<<1, 512>>>(kfcW, kfcb, out);
}

// round 2
// speedup vs baseline: 5.4028x; 5.4028x over previous
#include <cuda_runtime.h>
#include <math.h>
#include <stdint.h>

// ---------------- problem constants ----------------
#define T       4096
#define HID     400
#define G4      1600          // 4*HID
#define EMB     50
#define E3      150           // 3*EMB
#define KEY     300
#define K4      1200          // 4*KEY

// rtoken: T*E3 = 614400 floats; ktoken: 400; context: T*32*HID = 52428800
#define OFF_KTOK  614400
#define OFF_CTX   614800

#define L0_CTAS 20
#define L1_CTAS 40

// ---------------- scratch (static device globals; no allocation) ----------------
__device__ float    g_xg0[(size_t)T * G4];   // precomputed input gates layer0 (+both biases)
__device__ float    g_h0[(T + 1) * HID];     // h0 timeline, slot 0 = zeros
__device__ float    g_h1[(T + 1) * HID];     // h1 timeline (== rnn_out shifted by 1)
__device__ unsigned g_cnt0[(T + 1) * 32];    // per-slot ready counters (one 128B line each)
__device__ unsigned g_cnt1[(T + 1) * 32];
__device__ float    g_kgate[K4];             // key lstm pre-activation gates

// ---------------- helpers ----------------
__device__ __forceinline__ float sigf(float x) {
    return __fdividef(1.f, 1.f + __expf(-x));
}
__device__ __forceinline__ float tanhf_(float x) {
    x = fminf(15.f, fmaxf(-15.f, x));
    float e = __expf(-2.f * x);
    return __fdividef(1.f - e, 1.f + e);
}
__device__ __forceinline__ float wsum(float v) {
#pragma unroll
    for (int o = 16; o > 0; o >>= 1) v += __shfl_xor_sync(0xffffffffu, v, o);
    return v;
}
__device__ __forceinline__ unsigned ld_acq(const unsigned* p) {
    unsigned v;
    asm volatile("ld.acquire.gpu.global.u32 %0, [%1];" : "=r"(v) : "l"(p) : "memory");
    return v;
}
__device__ __forceinline__ void red_rel(unsigned* p) {
    asm volatile("red.release.gpu.global.add.u32 [%0], %1;" :: "l"(p), "r"(1u) : "memory");
}

// ---------------- init: counters + zero slot0 ----------------
__global__ void init_kernel() {
    int i = blockIdx.x * blockDim.x + threadIdx.x;
    if (i < (T + 1) * 32) {
        g_cnt0[i] = (i == 0) ? L0_CTAS : 0u;
        g_cnt1[i] = (i == 0) ? L1_CTAS : 0u;
    }
    if (i < HID) {
        g_h0[i] = 0.f;
        g_h1[i] = 0.f;
    }
}

// ---------------- kernel A: xg0 = concat-embed @ Wih0^T + bih0 + bhh0 ----------------
__global__ void __launch_bounds__(256, 1) xg0_kernel(
    const int* __restrict__ xr, const int* __restrict__ xcpc, const int* __restrict__ xma,
    const float* __restrict__ em, const float* __restrict__ ec, const float* __restrict__ er,
    const float* __restrict__ Wih0, const float* __restrict__ bih0, const float* __restrict__ bhh0)
{
    __shared__ float xs[64][53];
    __shared__ float ws[160][53];
    const int bt0 = blockIdx.x * 64;
    const int br0 = blockIdx.y * 160;
    const int tid = threadIdx.x;
    float acc[8][5];
#pragma unroll
    for (int i = 0; i < 8; i++)
#pragma unroll
        for (int r = 0; r < 5; r++) acc[i][r] = 0.f;

    for (int ch = 0; ch < 3; ch++) {
        const float* tab = (ch == 0) ? em : ((ch == 1) ? ec : er);
        const int* idx = (ch == 0) ? xma : ((ch == 1) ? xcpc : xr);
        for (int i = tid; i < 64 * 50; i += 256) {
            int tt = i / 50, kk = i - tt * 50;
            xs[tt][kk] = tab[idx[bt0 + tt] * EMB + kk];
        }
        for (int i = tid; i < 160 * 50; i += 256) {
            int rr = i / 50, kk = i - rr * 50;
            ws[rr][kk] = Wih0[(br0 + rr) * E3 + ch * 50 + kk];
        }
        __syncthreads();
        const int tr = tid & 31, tc = tid >> 5;
#pragma unroll 5
        for (int kk = 0; kk < 50; kk++) {
            float a[8], wv[5];
#pragma unroll
            for (int i = 0; i < 8; i++) a[i] = xs[tc * 8 + i][kk];
#pragma unroll
            for (int r = 0; r < 5; r++) wv[r] = ws[tr * 5 + r][kk];
#pragma unroll
            for (int i = 0; i < 8; i++)
#pragma unroll
                for (int r = 0; r < 5; r++) acc[i][r] = fmaf(a[i], wv[r], acc[i][r]);
        }
        __syncthreads();
    }
    const int tr = tid & 31, tc = tid >> 5;
#pragma unroll
    for (int r = 0; r < 5; r++) {
        int rg = br0 + tr * 5 + r;
        float bias = bih0[rg] + bhh0[rg];
#pragma unroll
        for (int i = 0; i < 8; i++) {
            int t = bt0 + tc * 8 + i;
            g_xg0[(size_t)t * G4 + rg] = acc[i][r] + bias;
        }
    }
}

// ---------------- kernel B: persistent dual-layer LSTM recurrence ----------------
// blocks 0..19:  layer0, 10 warps, each warp 2 cells (8 gate rows, K=400)
// blocks 20..59: layer1, 10 warps, each warp 1 cell  (4 gate rows, K=800: [Wih1|Whh1])
// sync: per-slot ready counters in private 128B lines; red.release / ld.acquire.
// production: gate pre-acts -> smem -> one cell-warp does nonlinearity + coalesced store.
__global__ void __launch_bounds__(320, 1) lstm_main_kernel(
    const float* __restrict__ Whh0,
    const float* __restrict__ Wih1,
    const float* __restrict__ Whh1,
    const float* __restrict__ bih1,
    const float* __restrict__ bhh1)
{
    const int warp = threadIdx.x >> 5;
    const int lane = threadIdx.x & 31;

    if (blockIdx.x < L0_CTAS) {
        // ---------------- layer 0 ----------------
        const int cta = blockIdx.x;
        const int jbase = cta * 20 + warp * 2;
        float w[8][13];                       // [jj*4+g][c]
#pragma unroll
        for (int jj = 0; jj < 2; jj++)
#pragma unroll
            for (int g = 0; g < 4; g++)
#pragma unroll
                for (int c = 0; c < 13; c++) {
                    int k = lane + 32 * c;
                    w[jj * 4 + g][c] = (k < HID) ? Whh0[(size_t)(jbase + jj + g * 400) * HID + k] : 0.f;
                }
        __shared__ float gbuf[2][20][4];
        const int cell = cta * 20 + lane;     // valid for warp0 lanes<20
        float cst = 0.f;

        for (int t = 0; t < T; t++) {
            // cell-warp prefetch of xg (independent of h -> overlaps poll)
            float x0 = 0.f, x1 = 0.f, x2 = 0.f, x3 = 0.f;
            if (warp == 0 && lane < 20) {
                const float* xg = g_xg0 + (size_t)t * G4 + cell;
                x0 = __ldg(xg); x1 = __ldg(xg + 400); x2 = __ldg(xg + 800); x3 = __ldg(xg + 1200);
            }
            // wait for h0[t]
            const unsigned* cp = g_cnt0 + (size_t)t * 32;
            while (ld_acq(cp) < L0_CTAS) {}
            // read h (coalesced, L2-homed)
            const float* hb = g_h0 + (size_t)t * HID;
            float hv[13];
#pragma unroll
            for (int c = 0; c < 13; c++) {
                int k = lane + 32 * c;
                hv[c] = (k < HID) ? __ldcg(hb + k) : 0.f;
            }
            float a[8];
#pragma unroll
            for (int r = 0; r < 8; r++) a[r] = 0.f;
#pragma unroll
            for (int c = 0; c < 13; c++)
#pragma unroll
                for (int r = 0; r < 8; r++) a[r] = fmaf(w[r][c], hv[c], a[r]);
#pragma unroll
            for (int r = 0; r < 8; r++) a[r] = wsum(a[r]);
            if (lane == 0) {
#pragma unroll
                for (int g = 0; g < 4; g++) {
                    gbuf[t & 1][warp * 2][g]     = a[g];
                    gbuf[t & 1][warp * 2 + 1][g] = a[4 + g];
                }
            }
            __syncthreads();
            if (warp == 0) {
                if (lane < 20) {
                    float gi = gbuf[t & 1][lane][0] + x0;
                    float gf = gbuf[t & 1][lane][1] + x1;
                    float gg = gbuf[t & 1][lane][2] + x2;
                    float go = gbuf[t & 1][lane][3] + x3;
                    cst = sigf(gf) * cst + sigf(gi) * tanhf_(gg);
                    float h = sigf(go) * tanhf_(cst);
                    __stcg(g_h0 + (size_t)(t + 1) * HID + cell, h);
                }
                __syncwarp();
                if (lane == 0) red_rel(g_cnt0 + (size_t)(t + 1) * 32);
            }
        }
    } else {
        // ---------------- layer 1 ----------------
        const int cta = blockIdx.x - L0_CTAS;
        const int j = cta * 10 + warp;
        float w[4][25];
#pragma unroll
        for (int g = 0; g < 4; g++)
#pragma unroll
            for (int c = 0; c < 25; c++) {
                int k = lane + 32 * c;
                int row = j + g * 400;
                w[g][c] = (k < HID) ? Wih1[(size_t)row * HID + k]
                                    : Whh1[(size_t)row * HID + (k - HID)];
            }
        __shared__ float gbuf[2][10][4];
        const int cell = cta * 10 + lane;     // valid for warp0 lanes<10
        float b0 = 0.f, b1 = 0.f, b2 = 0.f, b3 = 0.f, cst = 0.f;
        if (warp == 0 && lane < 10) {
            b0 = bih1[cell] + bhh1[cell];
            b1 = bih1[cell + 400] + bhh1[cell + 400];
            b2 = bih1[cell + 800] + bhh1[cell + 800];
            b3 = bih1[cell + 1200] + bhh1[cell + 1200];
        }

        for (int t = 0; t < T; t++) {
            // wait for h0[t] (slot t+1) and h1[t-1] (slot t)
            const unsigned* cp0 = g_cnt0 + (size_t)(t + 1) * 32;
            const unsigned* cp1 = g_cnt1 + (size_t)t * 32;
            while (ld_acq(cp0) < L0_CTAS) {}
            while (ld_acq(cp1) < L1_CTAS) {}
            const float* h0b = g_h0 + (size_t)(t + 1) * HID;
            const float* h1b = g_h1 + (size_t)t * HID;
            float hv[25];
#pragma unroll
            for (int c = 0; c < 25; c++) {
                int k = lane + 32 * c;
                hv[c] = __ldcg((k < HID) ? (h0b + k) : (h1b + (k - HID)));
            }
            float a0 = 0.f, a1 = 0.f, a2 = 0.f, a3 = 0.f;
#pragma unroll
            for (int c = 0; c < 25; c++) {
                a0 = fmaf(w[0][c], hv[c], a0);
                a1 = fmaf(w[1][c], hv[c], a1);
                a2 = fmaf(w[2][c], hv[c], a2);
                a3 = fmaf(w[3][c], hv[c], a3);
            }
            a0 = wsum(a0); a1 = wsum(a1); a2 = wsum(a2); a3 = wsum(a3);
            if (lane == 0) {
                gbuf[t & 1][warp][0] = a0;
                gbuf[t & 1][warp][1] = a1;
                gbuf[t & 1][warp][2] = a2;
                gbuf[t & 1][warp][3] = a3;
            }
            __syncthreads();
            if (warp == 0) {
                if (lane < 10) {
                    float gi = gbuf[t & 1][lane][0] + b0;
                    float gf = gbuf[t & 1][lane][1] + b1;
                    float gg = gbuf[t & 1][lane][2] + b2;
                    float go = gbuf[t & 1][lane][3] + b3;
                    cst = sigf(gf) * cst + sigf(gi) * tanhf_(gg);
                    float h = sigf(go) * tanhf_(cst);
                    __stcg(g_h1 + (size_t)(t + 1) * HID + cell, h);
                }
                __syncwarp();
                if (lane == 0) red_rel(g_cnt1 + (size_t)(t + 1) * 32);
            }
        }
    }
}

// ---------------- kernel C: rtoken = rnn_out @ fcW^T + fcb ----------------
__global__ void __launch_bounds__(256, 1) rtoken_kernel(
    const float* __restrict__ fcW, const float* __restrict__ fcb, float* __restrict__ out)
{
    __shared__ float xs[64][53];
    __shared__ float ws[160][53];
    const int bt0 = blockIdx.x * 64;
    const int tid = threadIdx.x;
    float acc[8][5];
#pragma unroll
    for (int i = 0; i < 8; i++)
#pragma unroll
        for (int r = 0; r < 5; r++) acc[i][r] = 0.f;

    for (int ch = 0; ch < 8; ch++) {
        int k0 = ch * 50;
        for (int i = tid; i < 64 * 50; i += 256) {
            int tt = i / 50, kk = i - tt * 50;
            xs[tt][kk] = g_h1[(size_t)(bt0 + tt + 1) * HID + k0 + kk];
        }
        for (int i = tid; i < 160 * 50; i += 256) {
            int rr = i / 50, kk = i - rr * 50;
            ws[rr][kk] = (rr < E3) ? fcW[rr * HID + k0 + kk] : 0.f;
        }
        __syncthreads();
        const int tr = tid & 31, tc = tid >> 5;
#pragma unroll 5
        for (int kk = 0; kk < 50; kk++) {
            float a[8], wv[5];
#pragma unroll
            for (int i = 0; i < 8; i++) a[i] = xs[tc * 8 + i][kk];
#pragma unroll
            for (int r = 0; r < 5; r++) wv[r] = ws[tr * 5 + r][kk];
#pragma unroll
            for (int i = 0; i < 8; i++)
#pragma unroll
                for (int r = 0; r < 5; r++) acc[i][r] = fmaf(a[i], wv[r], acc[i][r]);
        }
        __syncthreads();
    }
    const int tr = tid & 31, tc = tid >> 5;
#pragma unroll
    for (int r = 0; r < 5; r++) {
        int rg = tr * 5 + r;
        if (rg < E3) {
            float bias = fcb[rg];
#pragma unroll
            for (int i = 0; i < 8; i++) {
                int t = bt0 + tc * 8 + i;
                out[(size_t)t * E3 + rg] = acc[i][r] + bias;
            }
        }
    }
}

// ---------------- kernel D: context fill ----------------
__global__ void __launch_bounds__(128, 1) ctx_kernel(
    const float* __restrict__ actW, const float* __restrict__ actb,
    const float* __restrict__ Dp, float* __restrict__ out)
{
    const int t = blockIdx.x;
    const int warp = threadIdx.x >> 5, lane = threadIdx.x & 31;
    __shared__ float red[4];
    const float* hr = g_h1 + (size_t)(t + 1) * HID;
    const float* wrow = (warp < 3) ? (actW + warp * HID) : Dp;
    float acc = 0.f;
#pragma unroll
    for (int c = 0; c < 13; c++) {
        int k = lane + 32 * c;
        if (k < HID) acc = fmaf(__ldg(wrow + k), __ldg(hr + k), acc);
    }
    acc = wsum(acc);
    if (lane == 0) red[warp] = acc + ((warp < 3) ? actb[warp] : 0.f);
    __syncthreads();
    float l0 = red[0], l1 = red[1], l2 = red[2], d = red[3];
    float m = fmaxf(l0, fmaxf(l1, l2));
    float e0 = __expf(l0 - m), e1 = __expf(l1 - m), e2 = __expf(l2 - m);
    float p0 = __fdividef(e0, e0 + e1 + e2);
    float v = p0 * sigf(d);

    float4* dst = (float4*)(out + OFF_CTX + (size_t)t * 32 * HID);
    float4 vz = make_float4(v, v, v, v);
    float4 z = make_float4(0.f, 0.f, 0.f, 0.f);
    for (int q = threadIdx.x; q < 3200; q += 128) {
        __stcs(dst + q, (q < 100) ? vz : z);
    }
}

// ---------------- kernel E1: key lstm gates ----------------
__global__ void __launch_bounds__(128, 1) keygate_kernel(
    const float* __restrict__ kWih, const float* __restrict__ kbih, const float* __restrict__ kbhh)
{
    const int gw = blockIdx.x * 4 + (threadIdx.x >> 5);
    const int lane = threadIdx.x & 31;
    const float* hr = g_h1 + (size_t)T * HID;
    float hv[13];
#pragma unroll
    for (int c = 0; c < 13; c++) {
        int k = lane + 32 * c;
        hv[c] = (k < HID) ? __ldg(hr + k) : 0.f;
    }
    for (int rr = 0; rr < 30; rr++) {
        int r = gw * 30 + rr;
        float acc = 0.f;
#pragma unroll
        for (int c = 0; c < 13; c++) {
            int k = lane + 32 * c;
            if (k < HID) acc = fmaf(__ldg(kWih + (size_t)r * HID + k), hv[c], acc);
        }
        acc = wsum(acc);
        if (lane == 0) g_kgate[r] = acc + kbih[r] + kbhh[r];
    }
}

// ---------------- kernel E2: kh nonlinearity + ktoken ----------------
__global__ void __launch_bounds__(512, 1) keyout_kernel(
    const float* __restrict__ kfcW, const float* __restrict__ kfcb, float* __restrict__ out)
{
    __shared__ float kh[KEY];
    const int tid = threadIdx.x;
    if (tid < KEY) {
        float gi = g_kgate[tid], gg = g_kgate[600 + tid], go = g_kgate[900 + tid];
        float c = sigf(gi) * tanhf_(gg);
        kh[tid] = sigf(go) * tanhf_(c);
    }
    __syncthreads();
    const int warp = tid >> 5, lane = tid & 31;
    for (int rr = 0; rr < 25; rr++) {
        int r = warp * 25 + rr;
        float acc = 0.f;
#pragma unroll
        for (int c = 0; c < 10; c++) {
            int k = lane + 32 * c;
            if (k < KEY) acc = fmaf(__ldg(kfcW + (size_t)r * KEY + k), kh[k], acc);
        }
        acc = wsum(acc);
        if (lane == 0) out[OFF_KTOK + r] = acc + kfcb[r];
    }
}

// ---------------- launch ----------------
extern "C" void kernel_launch(void* const* d_in, const int* in_sizes, int n_in,
                              void* d_out, int out_size)
{
    const int*   xr       = (const int*)d_in[0];
    const int*   xcpc     = (const int*)d_in[1];
    const int*   xma      = (const int*)d_in[2];
    const float* em       = (const float*)d_in[3];
    const float* ec       = (const float*)d_in[4];
    const float* er       = (const float*)d_in[5];
    const float* Wih0     = (const float*)d_in[6];
    const float* Whh0     = (const float*)d_in[7];
    const float* bih0     = (const float*)d_in[8];
    const float* bhh0     = (const float*)d_in[9];
    const float* Wih1     = (const float*)d_in[10];
    const float* Whh1     = (const float*)d_in[11];
    const float* bih1     = (const float*)d_in[12];
    const float* bhh1     = (const float*)d_in[13];
    const float* fcW      = (const float*)d_in[14];
    const float* fcb      = (const float*)d_in[15];
    const float* actW     = (const float*)d_in[16];
    const float* actb     = (const float*)d_in[17];
    const float* Dp       = (const float*)d_in[18];
    const float* kWih     = (const float*)d_in[19];
    const float* kbih     = (const float*)d_in[21];
    const float* kbhh     = (const float*)d_in[22];
    const float* kfcW     = (const float*)d_in[23];
    const float* kfcb     = (const float*)d_in[24];
    float* out = (float*)d_out;

    init_kernel<<<((T + 1) * 32 + 255) / 256, 256>>>();
    xg0_kernel<<<dim3(T / 64, G4 / 160), 256>>>(xr, xcpc, xma, em, ec, er, Wih0, bih0, bhh0);
    lstm_main_kernel<<<L0_CTAS + L1_CTAS, 320>>>(Whh0, Wih1, Whh1, bih1, bhh1);
    rtoken_kernel<<<T / 64, 256>>>(fcW, fcb, out);
    ctx_kernel<<<T, 128>>>(actW, actb, Dp, out);
    keygate_kernel<<<10, 128>>>(kWih, kbih, kbhh);
    keyout_kernel<<<1, 512>>>(kfcW, kfcb, out);
}